// round 5
// baseline (speedup 1.0000x reference)
#include <cuda_runtime.h>
#include <math.h>

#define Bsz 4
#define AT 128
#define NBR 20
#define NK 19
#define R2 (Bsz*AT*NBR)        // 10240 edge rows
#define NODES (Bsz*AT)         // 512
#define CNT3 (R2*NK)           // 194560 three-body rows
#define OFF3 (256*256)         // BN3 partial offset in d_psum/d_psq

// ---------------- scratch (static device globals; no allocation) ----------------
__device__ float d_Y2[R2*256];        // two-body pre-BN GEMM output
__device__ float d_PN[NODES*768];     // node @ [W3a|W3b|W3c]
__device__ float d_QE[R2*512];        // edge @ [W3d|W3e]
__device__ float d_TB[R2*128];        // three-body pre-final-BN sums
__device__ float d_S[NODES*256];      // per-node sum of w over its 20 neighbors
__device__ float d_Q[NODES*256];      // per-node sum of w^2
__device__ float d_psum[OFF3 + 640*256];
__device__ float d_psq [OFF3 + 640*256];
__device__ float d_pSs[1280*128];     // final-BN partials (from pass2 epilogue)
__device__ float d_pSq[1280*128];
__device__ float d_scale2[256], d_shift2[256];
__device__ float d_scale3[256], d_shift3[256];
__device__ float d_scaleS[128], d_shiftS[128];

__device__ __forceinline__ float tanh_hw(float x) {
    float y; asm("tanh.approx.f32 %0, %1;" : "=f"(y) : "f"(x)); return y;
}
__device__ __forceinline__ float sigmoid_hw(float x) {
    return fmaf(tanh_hw(0.5f*x), 0.5f, 0.5f);
}
__device__ __forceinline__ float sigmoidf_(float x) { return 1.f/(1.f + __expf(-x)); }

// ---------------- one fused GEMM launch for PN, QE, Y2 ----------------
__global__ void __launch_bounds__(256) gemm_all(
    const float* __restrict__ node, const float* __restrict__ edge,
    const int* __restrict__ nbr_idx, const int* __restrict__ nbr_mask,
    const float* __restrict__ W2, const float* __restrict__ W3) {
    __shared__ float Ast[64][65];   // transposed: Ast[k][m]
    __shared__ float Bs[64][64];
    __shared__ int   sRI[64];
    __shared__ int   sRJ[64];
    __shared__ float sM[64];
    int tid = threadIdx.x;
    int txx = tid & 15, tym = tid >> 4;
    int xt = blockIdx.x, yt = blockIdx.y;

    const float* A; const float* Bp; float* C;
    int ldc, cbase, m0, n0, mode;
    if (yt >= 160) {                       // PN
        mode = 2; m0 = (yt - 160)*64; n0 = xt*64;
        A = node; Bp = W3 + (n0 >> 8)*(128*256); cbase = n0 & 255;
        C = d_PN; ldc = 768;
    } else if (xt < 8) {                   // QE
        mode = 0; m0 = yt*64; n0 = xt*64;
        A = edge; Bp = W3 + (3 + (n0 >> 8))*(128*256); cbase = n0 & 255;
        C = d_QE; ldc = 512;
    } else {                               // Y2 (c2 fused)
        mode = 1; m0 = yt*64; n0 = (xt - 8)*64;
        A = node; Bp = W2; cbase = n0;
        C = d_Y2; ldc = 256;
        if (tid < 64) {
            int r = m0 + tid;
            int j = nbr_idx[r];
            int b = r / (AT*NBR);
            sRI[tid] = (r / NBR)*128;
            sRJ[tid] = (b*AT + j)*128;
            sM[tid]  = (float)nbr_mask[r];
        }
        __syncthreads();
    }

    float acc[4][4] = {};
    for (int k0 = 0; k0 < 128; k0 += 64) {
        if (mode == 1) {
            #pragma unroll
            for (int l = 0; l < 16; l++) {
                int e = l*256 + tid;
                int m = e >> 6, k = e & 63;
                Ast[k][m] = node[sRI[m] + k0 + k] * node[sRJ[m] + k0 + k] * sM[m];
            }
        } else {
            #pragma unroll
            for (int l = 0; l < 16; l++) {
                int e = l*256 + tid;
                int m = e >> 6, k = e & 63;
                Ast[k][m] = A[(m0 + m)*128 + k0 + k];
            }
        }
        #pragma unroll
        for (int l = 0; l < 16; l++) {
            int e = l*256 + tid;
            int k = e >> 6, n = e & 63;
            Bs[k][n] = Bp[(k0 + k)*256 + cbase + n];
        }
        __syncthreads();
        #pragma unroll 8
        for (int kk = 0; kk < 64; kk++) {
            float a0 = Ast[kk][tym*4+0];
            float a1 = Ast[kk][tym*4+1];
            float a2 = Ast[kk][tym*4+2];
            float a3 = Ast[kk][tym*4+3];
            float4 bv = *(const float4*)&Bs[kk][txx*4];
            acc[0][0] = fmaf(a0, bv.x, acc[0][0]); acc[0][1] = fmaf(a0, bv.y, acc[0][1]);
            acc[0][2] = fmaf(a0, bv.z, acc[0][2]); acc[0][3] = fmaf(a0, bv.w, acc[0][3]);
            acc[1][0] = fmaf(a1, bv.x, acc[1][0]); acc[1][1] = fmaf(a1, bv.y, acc[1][1]);
            acc[1][2] = fmaf(a1, bv.z, acc[1][2]); acc[1][3] = fmaf(a1, bv.w, acc[1][3]);
            acc[2][0] = fmaf(a2, bv.x, acc[2][0]); acc[2][1] = fmaf(a2, bv.y, acc[2][1]);
            acc[2][2] = fmaf(a2, bv.z, acc[2][2]); acc[2][3] = fmaf(a2, bv.w, acc[2][3]);
            acc[3][0] = fmaf(a3, bv.x, acc[3][0]); acc[3][1] = fmaf(a3, bv.y, acc[3][1]);
            acc[3][2] = fmaf(a3, bv.z, acc[3][2]); acc[3][3] = fmaf(a3, bv.w, acc[3][3]);
        }
        __syncthreads();
    }
    #pragma unroll
    for (int i = 0; i < 4; i++)
        #pragma unroll
        for (int jj = 0; jj < 4; jj++)
            C[(m0 + tym*4 + i)*ldc + n0 + txx*4 + jj] = acc[i][jj];

    // fused BN2 tile stats (Y2 tiles only)
    if (mode == 1) {
        #pragma unroll
        for (int jj = 0; jj < 4; jj++) {
            float s = 0.f, q = 0.f;
            #pragma unroll
            for (int i = 0; i < 4; i++) {
                float v = acc[i][jj];
                s += v; q = fmaf(v, v, q);
            }
            Ast[tym][txx*4+jj] = s;
            Bs [tym][txx*4+jj] = q;
        }
        __syncthreads();
        if (tid < 64) {
            float s = 0.f, q = 0.f;
            #pragma unroll
            for (int t = 0; t < 16; t++) { s += Ast[t][tid]; q += Bs[t][tid]; }
            d_psum[yt*256 + n0 + tid] = s;
            d_psq [yt*256 + n0 + tid] = q;
        }
    }
}

// ---------------- per-node neighbor aggregate: S_j, Q_j over all 20 neighbors ----------------
__global__ void k_nodeagg(const int* __restrict__ nbr_idx) {
    int c = threadIdx.x;
    int bj = blockIdx.x;
    int b = bj >> 7;
    int jrow = bj * NBR;
    float s = 0.f, q = 0.f;
    #pragma unroll
    for (int m = 0; m < NBR; m++) {
        int vk = nbr_idx[jrow + m];
        float w = d_PN[(b*AT + vk)*768 + 512 + c] + d_QE[(jrow + m)*512 + 256 + c];
        s += w; q = fmaf(w, w, q);
    }
    d_S[bj*256 + c] = s;
    d_Q[bj*256 + c] = q;
}

// ---------------- three-body pass 1 (closed form): stats over 194,560 combos ----------------
__global__ void k_pass1(const int* __restrict__ nbr_idx) {
    int c = threadIdx.x;
    float s = 0.f, q = 0.f;
    for (int i = 0; i < 16; i++) {
        int r = blockIdx.x*16 + i;
        int n = r % NBR;
        int ba = r / NBR;
        int b = ba >> 7;
        int j = nbr_idx[r];
        int bj = b*AT + j;
        int jrow = bj*NBR;
        float base = d_PN[ba*768 + c] + d_PN[bj*768 + 256 + c] + d_QE[r*512 + c];
        int vkn = nbr_idx[jrow + n];
        float wn = d_PN[(b*AT + vkn)*768 + 512 + c] + d_QE[(jrow + n)*512 + 256 + c];
        float Sm = d_S[bj*256 + c] - wn;
        float Qm = d_Q[bj*256 + c] - wn*wn;
        s += fmaf((float)NK, base, Sm);
        q += fmaf((float)NK*base + 2.f*Sm, base, Qm);
    }
    d_psum[OFF3 + blockIdx.x*256 + c] = s;
    d_psq [OFF3 + blockIdx.x*256 + c] = q;
}

// ---------------- coalesced block BN finalize ----------------
// block owns 32 consecutive channels; 256 threads = 8 part-rows x 32 lanes
__device__ __forceinline__ void fin_block(int c0,
        const float* __restrict__ ps, const float* __restrict__ pq,
        int ch, int parts, float cnt,
        const float* __restrict__ gamma, const float* __restrict__ beta,
        float* scale, float* shift) {
    __shared__ float sS[256], sQ[256];
    int tid = threadIdx.x;
    int lane = tid & 31, pr = tid >> 5;
    int c = c0 + lane;
    float s = 0.f, q = 0.f;
    for (int p = pr; p < parts; p += 8) {
        s += ps[p*ch + c];
        q += pq[p*ch + c];
    }
    sS[tid] = s; sQ[tid] = q;
    __syncthreads();
    if (tid < 32) {
        #pragma unroll
        for (int w = 1; w < 8; w++) { s += sS[w*32 + tid]; q += sQ[w*32 + tid]; }
        float mean = s / cnt;
        float var  = q / cnt - mean*mean;
        float sc = gamma[c0 + tid] * rsqrtf(var + 1e-5f);
        scale[c0 + tid] = sc;
        shift[c0 + tid] = beta[c0 + tid] - mean * sc;
    }
}

// grid 16: blocks 0..7 -> BN2 (parts=160), 8..15 -> BN3 (parts=640)
__global__ void k_fin23(const float* __restrict__ g2, const float* __restrict__ be2,
                        const float* __restrict__ g3, const float* __restrict__ be3) {
    if (blockIdx.x < 8)
        fin_block(blockIdx.x*32, d_psum, d_psq, 256, 160, (float)R2, g2, be2, d_scale2, d_shift2);
    else
        fin_block((blockIdx.x-8)*32, d_psum + OFF3, d_psq + OFF3, 256, 640, (float)CNT3, g3, be3, d_scale3, d_shift3);
}

// grid 4: final BN over 1280 parts of 128 channels
__global__ void k_finS(const float* __restrict__ gs, const float* __restrict__ bes) {
    fin_block(blockIdx.x*32, d_pSs, d_pSq, 128, 1280, (float)R2, gs, bes, d_scaleS, d_shiftS);
}

// ---------------- three-body pass 2: warp-per-row, float4 channels ----------------
// grid 1280 x 256 threads (8 warps = 8 rows); lane owns channels 4l..4l+3 (g) and +128 (e)
// epilogue: per-block final-BN stats partials (fuses old k_stats_part128)
__global__ void __launch_bounds__(256) k_pass2(const int* __restrict__ nbr_idx) {
    __shared__ float sS[8][128];
    __shared__ float sQ[8][128];
    int wid = threadIdx.x >> 5, lane = threadIdx.x & 31;
    int r = blockIdx.x*8 + wid;
    int n = r % NBR;
    int ba = r / NBR;
    int b = ba >> 7;
    int j = nbr_idx[r];
    int bj = b*AT + j;
    int jrow = bj*NBR;
    int offPN = 0, offQE = 0;
    if (lane < NK) {
        int m = lane + (lane >= n);
        int vk = nbr_idx[jrow + m];
        offPN = (b*AT + vk)*768;
        offQE = (jrow + m)*512;
    }
    const float4* PNa = (const float4*)(d_PN + ba*768);
    const float4* PNj = (const float4*)(d_PN + bj*768);
    const float4* QEr = (const float4*)(d_QE + r*512);
    float4 sg = ((const float4*)d_scale3)[lane];
    float4 hg = ((const float4*)d_shift3)[lane];
    float4 se = ((const float4*)d_scale3)[32 + lane];
    float4 he = ((const float4*)d_shift3)[32 + lane];
    float4 pag = PNa[lane],      pjg = PNj[64 + lane], qeg = QEr[lane];
    float4 pae = PNa[32 + lane], pje = PNj[96 + lane], qee = QEr[32 + lane];
    float4 baseg, basee;
    baseg.x = fmaf(sg.x, pag.x + pjg.x + qeg.x, hg.x);
    baseg.y = fmaf(sg.y, pag.y + pjg.y + qeg.y, hg.y);
    baseg.z = fmaf(sg.z, pag.z + pjg.z + qeg.z, hg.z);
    baseg.w = fmaf(sg.w, pag.w + pjg.w + qeg.w, hg.w);
    basee.x = fmaf(se.x, pae.x + pje.x + qee.x, he.x);
    basee.y = fmaf(se.y, pae.y + pje.y + qee.y, he.y);
    basee.z = fmaf(se.z, pae.z + pje.z + qee.z, he.z);
    basee.w = fmaf(se.w, pae.w + pje.w + qee.w, he.w);

    float4 acc = make_float4(0.f, 0.f, 0.f, 0.f);
    #pragma unroll
    for (int k = 0; k < NK; k++) {
        int oPN = __shfl_sync(0xffffffffu, offPN, k);
        int oQE = __shfl_sync(0xffffffffu, offQE, k);
        float4 g4 = *(const float4*)(d_PN + oPN + 512 + 4*lane);
        float4 q4 = *(const float4*)(d_QE + oQE + 256 + 4*lane);
        float4 e4 = *(const float4*)(d_PN + oPN + 640 + 4*lane);
        float4 r4 = *(const float4*)(d_QE + oQE + 384 + 4*lane);
        float gx = fmaf(sg.x, g4.x + q4.x, baseg.x);
        float gy = fmaf(sg.y, g4.y + q4.y, baseg.y);
        float gz = fmaf(sg.z, g4.z + q4.z, baseg.z);
        float gw = fmaf(sg.w, g4.w + q4.w, baseg.w);
        float ex = fmaf(se.x, e4.x + r4.x, basee.x);
        float ey = fmaf(se.y, e4.y + r4.y, basee.y);
        float ez = fmaf(se.z, e4.z + r4.z, basee.z);
        float ew = fmaf(se.w, e4.w + r4.w, basee.w);
        acc.x += sigmoid_hw(gx) * tanh_hw(ex);
        acc.y += sigmoid_hw(gy) * tanh_hw(ey);
        acc.z += sigmoid_hw(gz) * tanh_hw(ez);
        acc.w += sigmoid_hw(gw) * tanh_hw(ew);
    }
    ((float4*)(d_TB + r*128))[lane] = acc;
    ((float4*)sS[wid])[lane] = acc;
    float4 a2 = make_float4(acc.x*acc.x, acc.y*acc.y, acc.z*acc.z, acc.w*acc.w);
    ((float4*)sQ[wid])[lane] = a2;
    __syncthreads();
    if (threadIdx.x < 128) {
        float s = 0.f, q = 0.f;
        #pragma unroll
        for (int w = 0; w < 8; w++) { s += sS[w][threadIdx.x]; q += sQ[w][threadIdx.x]; }
        d_pSs[blockIdx.x*128 + threadIdx.x] = s;
        d_pSq[blockIdx.x*128 + threadIdx.x] = q;
    }
}

// ---------------- final: out = tanh(edge + two_body + BN(three_body)), float4 ----------------
__global__ void k_out(const float* __restrict__ edge, float* __restrict__ out) {
    int idx = blockIdx.x*256 + threadIdx.x;     // float4 index over R2*128/4
    if (idx >= R2*32) return;
    int cl = idx & 31;          // float4 channel (c = 4*cl)
    int r = idx >> 5;
    float4 yg = ((const float4*)d_Y2)[r*64 + cl];
    float4 ye = ((const float4*)d_Y2)[r*64 + 32 + cl];
    float4 tb = ((const float4*)d_TB)[idx];
    float4 eg = ((const float4*)edge)[idx];
    float4 s2g = ((const float4*)d_scale2)[cl],      h2g = ((const float4*)d_shift2)[cl];
    float4 s2e = ((const float4*)d_scale2)[32 + cl], h2e = ((const float4*)d_shift2)[32 + cl];
    float4 sS4 = ((const float4*)d_scaleS)[cl],      hS4 = ((const float4*)d_shiftS)[cl];
    float4 o;
    o.x = tanhf(eg.x + sigmoidf_(fmaf(s2g.x, yg.x, h2g.x))*tanhf(fmaf(s2e.x, ye.x, h2e.x)) + fmaf(sS4.x, tb.x, hS4.x));
    o.y = tanhf(eg.y + sigmoidf_(fmaf(s2g.y, yg.y, h2g.y))*tanhf(fmaf(s2e.y, ye.y, h2e.y)) + fmaf(sS4.y, tb.y, hS4.y));
    o.z = tanhf(eg.z + sigmoidf_(fmaf(s2g.z, yg.z, h2g.z))*tanhf(fmaf(s2e.z, ye.z, h2e.z)) + fmaf(sS4.z, tb.z, hS4.z));
    o.w = tanhf(eg.w + sigmoidf_(fmaf(s2g.w, yg.w, h2g.w))*tanhf(fmaf(s2e.w, ye.w, h2e.w)) + fmaf(sS4.w, tb.w, hS4.w));
    ((float4*)out)[idx] = o;
}

// ---------------- launch ----------------
extern "C" void kernel_launch(void* const* d_in, const int* in_sizes, int n_in,
                              void* d_out, int out_size) {
    const float* node     = (const float*)d_in[0];
    const float* edge     = (const float*)d_in[1];
    const int*   nbr_idx  = (const int*)  d_in[2];
    const int*   nbr_mask = (const int*)  d_in[3];
    const float* W2       = (const float*)d_in[4];
    const float* W3       = (const float*)d_in[6];
    const float* g2  = (const float*)d_in[8];
    const float* be2 = (const float*)d_in[9];
    const float* g3  = (const float*)d_in[10];
    const float* be3 = (const float*)d_in[11];
    const float* gs  = (const float*)d_in[12];
    const float* bes = (const float*)d_in[13];
    float* out = (float*)d_out;

    // 1. all GEMMs (PN, QE, Y2 + fused BN2 stats)
    gemm_all<<<dim3(12, 168), 256>>>(node, edge, nbr_idx, nbr_mask, W2, W3);

    // 2. per-node neighbor aggregates S_j, Q_j
    k_nodeagg<<<NODES, 256>>>(nbr_idx);

    // 3. three-body pass 1 (closed-form BN3 stats)
    k_pass1<<<640, 256>>>(nbr_idx);

    // 4. finalize BN2 + BN3 (coalesced)
    k_fin23<<<16, 256>>>(g2, be2, g3, be3);

    // 5. three-body pass 2 (warp-per-row, float4; fused final-BN stats)
    k_pass2<<<1280, 256>>>(nbr_idx);

    // 6. finalize final BN (coalesced)
    k_finS<<<4, 256>>>(gs, bes);

    // 7. output
    k_out<<<1280, 256>>>(edge, out);
}